// round 1
// baseline (speedup 1.0000x reference)
#include <cuda_runtime.h>
#include <cuda_bf16.h>
#include <math.h>

// Problem constants (fixed by setup_inputs)
#define Bv   32
#define Cc   256
#define Nn   64
#define NNv  4096
#define Sv   64
#define Pv   2080          // triu(64x64) count
#define TPv  128           // positions per K2 block
#define CHv  8             // c-chunk
#define NTILE 17           // ceil(2080/128)

typedef unsigned long long u64;

union F2 { u64 u; float2 f; };

__device__ __forceinline__ void fma2(u64 &acc, u64 a, u64 b) {
    asm("fma.rn.f32x2 %0, %1, %2, %0;" : "+l"(acc) : "l"(a), "l"(b));
}

// -------- device scratch (no allocations allowed) --------
__device__ int   g_flat[Pv];            // compacted triu flat positions
__device__ int   g_scatter[Sv];         // sentence -> video index
__device__ int   g_toppos[Sv];          // argmax-iou flat position per sentence
__device__ float g_sfdup[Cc * 2 * Sv];  // [c][2s] duplicated normalized sentence feats
__device__ float g_part[Bv * NTILE * Sv]; // per-block partial neg sums (deterministic)
__device__ float g_lv[Sv];              // inter-video loss per sentence
__device__ float g_posS[Sv];            // inter_video_pos per sentence

// ============================================================
// K1: build flat idx (triu), scatter idx, normalized sentence
//     feats (duplicated layout), and per-sentence iou argmax.
// ============================================================
__global__ void k1_setup(const float* __restrict__ sents,
                         const int*   __restrict__ num_targets,
                         const float* __restrict__ iou) {
    int tid = threadIdx.x;               // 256 threads
    int w = tid >> 5, lane = tid & 31;

    // 1. triu flat index list (row-major, matches np.nonzero order)
    if (tid < Nn) {
        int r = tid;
        int off = r * Nn - (r * (r - 1)) / 2;   // sum_{r'<r}(Nn - r')
        for (int c = r; c < Nn; c++) g_flat[off++] = r * Nn + c;
    }

    // 2. scatter idx (serial, tiny)
    if (tid == 0) {
        int s = 0;
        for (int b = 0; b < Bv && s < Sv; b++) {
            int n = num_targets[b];
            for (int k = 0; k < n && s < Sv; k++) g_scatter[s++] = b;
        }
    }

    // 3. normalize sentence feats, store duplicated-transposed [c][2s]
    for (int s = w; s < Sv; s += 8) {
        float vs[8]; float ss = 0.f;
        #pragma unroll
        for (int k = 0; k < 8; k++) {
            float v = sents[s * Cc + lane + k * 32];
            vs[k] = v; ss += v * v;
        }
        #pragma unroll
        for (int o = 16; o; o >>= 1) ss += __shfl_xor_sync(0xffffffffu, ss, o);
        float rn = 1.f / fmaxf(sqrtf(ss), 1e-12f);
        #pragma unroll
        for (int k = 0; k < 8; k++) {
            int c = lane + k * 32;
            float v = vs[k] * rn;
            g_sfdup[c * (2 * Sv) + 2 * s]     = v;
            g_sfdup[c * (2 * Sv) + 2 * s + 1] = v;
        }
    }
    __syncthreads();   // g_flat ready for step 4

    // 4. per-sentence argmax of iou over compacted list (lowest index wins ties)
    for (int s = w; s < Sv; s += 8) {
        float bv = -1e30f; int bi = 0x3fffffff;
        for (int i = lane; i < Pv; i += 32) {
            float v = iou[s * NNv + g_flat[i]];
            if (v > bv || (v == bv && i < bi)) { bv = v; bi = i; }
        }
        #pragma unroll
        for (int o = 16; o; o >>= 1) {
            float ov = __shfl_xor_sync(0xffffffffu, bv, o);
            int   oi = __shfl_xor_sync(0xffffffffu, bi, o);
            if (ov > bv || (ov == bv && oi < bi)) { bv = ov; bi = oi; }
        }
        if (lane == 0) g_toppos[s] = g_flat[bi];
    }
}

// ============================================================
// K2: fused GEMM (scores for all 64 sentences x 128 positions
//     per block, one video b per blockIdx.y) + column norms +
//     exp/neg-mask reduction to per-block partials.
//     f32x2 packed FMA: acc pair = (pos 2p, 2p+1) per sentence.
// ============================================================
__global__ void __launch_bounds__(128)
k2_gemm(const float* __restrict__ V, const float* __restrict__ iou) {
    int tile = blockIdx.x;
    int b    = blockIdx.y;
    int p0   = tile * TPv;

    __shared__ __align__(16) float sh_v[CHv][TPv];
    __shared__ __align__(16) float sh_sf[CHv][2 * Sv];
    __shared__ int   sh_flat[TPv];
    __shared__ float sh_rn[TPv];
    __shared__ float sh_part[Sv][16];

    int tid = threadIdx.x;          // 128
    int tx = tid & 15;              // pos group (8 pos each)
    int ty = tid >> 4;              // sentence group (8 s each)

    {
        int p = p0 + tid;
        sh_flat[tid] = (p < Pv) ? g_flat[p] : -1;
    }
    __syncthreads();
    int ldf = sh_flat[tid];         // this thread's load position
    int myf[8];
    #pragma unroll
    for (int j = 0; j < 8; j++) myf[j] = sh_flat[tx * 8 + j];

    u64 acc[8][4];
    #pragma unroll
    for (int i = 0; i < 8; i++)
        #pragma unroll
        for (int k = 0; k < 4; k++) acc[i][k] = 0ull;
    u64 nacc[4] = {0ull, 0ull, 0ull, 0ull};

    const float* Vb = V + (size_t)b * Cc * NNv;

    for (int c0 = 0; c0 < Cc; c0 += CHv) {
        __syncthreads();
        #pragma unroll
        for (int cc = 0; cc < CHv; cc++) {
            sh_v[cc][tid]  = (ldf >= 0) ? Vb[(c0 + cc) * NNv + ldf] : 0.f;
            sh_sf[cc][tid] = g_sfdup[(c0 + cc) * (2 * Sv) + tid];
        }
        __syncthreads();
        #pragma unroll
        for (int cc = 0; cc < CHv; cc++) {
            ulonglong2 va  = *reinterpret_cast<const ulonglong2*>(&sh_v[cc][tx * 8]);
            ulonglong2 vb2 = *reinterpret_cast<const ulonglong2*>(&sh_v[cc][tx * 8 + 4]);
            ulonglong2 s01 = *reinterpret_cast<const ulonglong2*>(&sh_sf[cc][ty * 16]);
            ulonglong2 s23 = *reinterpret_cast<const ulonglong2*>(&sh_sf[cc][ty * 16 + 4]);
            ulonglong2 s45 = *reinterpret_cast<const ulonglong2*>(&sh_sf[cc][ty * 16 + 8]);
            ulonglong2 s67 = *reinterpret_cast<const ulonglong2*>(&sh_sf[cc][ty * 16 + 12]);
            u64 sd[8] = {s01.x, s01.y, s23.x, s23.y, s45.x, s45.y, s67.x, s67.y};
            #pragma unroll
            for (int si = 0; si < 8; si++) {
                fma2(acc[si][0], va.x,  sd[si]);
                fma2(acc[si][1], va.y,  sd[si]);
                fma2(acc[si][2], vb2.x, sd[si]);
                fma2(acc[si][3], vb2.y, sd[si]);
            }
            if (ty == 0) {   // norms: 1/8 of threads, negligible extra FMA
                fma2(nacc[0], va.x,  va.x);
                fma2(nacc[1], va.y,  va.y);
                fma2(nacc[2], vb2.x, vb2.x);
                fma2(nacc[3], vb2.y, vb2.y);
            }
        }
    }

    if (ty == 0) {
        #pragma unroll
        for (int k = 0; k < 4; k++) {
            F2 u; u.u = nacc[k];
            sh_rn[tx * 8 + 2 * k]     = 1.f / fmaxf(sqrtf(u.f.x), 1e-12f);
            sh_rn[tx * 8 + 2 * k + 1] = 1.f / fmaxf(sqrtf(u.f.y), 1e-12f);
        }
    }
    __syncthreads();

    float rn[8];
    #pragma unroll
    for (int j = 0; j < 8; j++) rn[j] = sh_rn[tx * 8 + j];

    #pragma unroll
    for (int si = 0; si < 8; si++) {
        int s = ty * 8 + si;
        bool samevid = (g_scatter[s] == b);
        float d[8];
        #pragma unroll
        for (int k = 0; k < 4; k++) {
            F2 u; u.u = acc[si][k];
            d[2 * k] = u.f.x; d[2 * k + 1] = u.f.y;
        }
        float part = 0.f;
        #pragma unroll
        for (int j = 0; j < 8; j++) {
            int fp = myf[j];
            if (fp < 0) continue;
            if (samevid && iou[s * NNv + fp] > 0.5f) continue;  // positive -> excluded
            part += __expf(d[j] * rn[j] * 10.0f);               // exp(score / 0.1)
        }
        sh_part[s][tx] = part;
    }
    __syncthreads();

    if (tid < Sv) {
        float sum = 0.f;
        #pragma unroll
        for (int k = 0; k < 16; k++) sum += sh_part[tid][k];
        g_part[((size_t)b * NTILE + tile) * Sv + tid] = sum;
    }
}

// ============================================================
// K3: inter-video loss. Block s: take its top-iou proposal's
//     normalized column, dot with all 64 sentences, softmax-CE.
// ============================================================
__global__ void k3_intervideo(const float* __restrict__ V) {
    int s = blockIdx.x;
    int t = threadIdx.x;   // 64 threads
    __shared__ float sh_col[Cc];
    __shared__ float sh_red[64];
    __shared__ float sh_e[64];
    __shared__ float sh_posv;

    int b   = g_scatter[s];
    int pos = g_toppos[s];
    const float* Vb = V + (size_t)b * Cc * NNv + pos;

    float ss = 0.f;
    #pragma unroll
    for (int k = 0; k < 4; k++) {
        float v = Vb[(size_t)(t + 64 * k) * NNv];
        sh_col[t + 64 * k] = v;
        ss += v * v;
    }
    sh_red[t] = ss;
    __syncthreads();
    #pragma unroll
    for (int o = 32; o; o >>= 1) {
        if (t < o) sh_red[t] += sh_red[t + o];
        __syncthreads();
    }
    float rnorm = 1.f / fmaxf(sqrtf(sh_red[0]), 1e-12f);

    float dot = 0.f;
    #pragma unroll 8
    for (int c = 0; c < Cc; c++) dot += sh_col[c] * g_sfdup[c * (2 * Sv) + 2 * t];
    float A = dot * rnorm;

    if (t == s) sh_posv = A;
    sh_e[t] = (t == s) ? 0.f : __expf(A * 10.0f);   // exp(score / 0.1)
    __syncthreads();

    if (t == 0) {
        float ns = 0.f;
        for (int i = 0; i < 64; i++) ns += sh_e[i];
        float ps = sh_posv;
        float pe = __expf(ps * 10.0f);
        g_lv[s]   = logf(pe + ns) - ps * 10.0f;
        g_posS[s] = ps;
    }
}

// ============================================================
// K4: final deterministic reductions -> two scalar losses.
// ============================================================
__global__ void k4_final(float* __restrict__ out) {
    __shared__ float sh[64];
    int t = threadIdx.x;   // 64

    float ns = 0.f;
    for (int b = 0; b < Bv; b++)
        for (int tl = 0; tl < NTILE; tl++)
            ns += g_part[((size_t)b * NTILE + tl) * Sv + t];
    float ps = g_posS[t];
    float pe = __expf(ps * 10.0f);
    float lq = logf(pe + ns) - ps * 10.0f;

    sh[t] = lq;
    __syncthreads();
    #pragma unroll
    for (int o = 32; o; o >>= 1) {
        if (t < o) sh[t] += sh[t + o];
        __syncthreads();
    }
    if (t == 0) out[1] = sh[0] / 64.0f;
    __syncthreads();

    sh[t] = g_lv[t];
    __syncthreads();
    #pragma unroll
    for (int o = 32; o; o >>= 1) {
        if (t < o) sh[t] += sh[t + o];
        __syncthreads();
    }
    if (t == 0) out[0] = sh[0] / 64.0f;
}

// ============================================================
extern "C" void kernel_launch(void* const* d_in, const int* in_sizes, int n_in,
                              void* d_out, int out_size) {
    const float* video = (const float*)d_in[0];   // [32,256,64,64]
    const float* sents = (const float*)d_in[1];   // [64,256]
    const int*   ntg   = (const int*)  d_in[2];   // [32]
    const float* iou   = (const float*)d_in[3];   // [64,64,64]
    // d_in[4] = mask2d (structural triu constant; rebuilt analytically in K1)

    k1_setup<<<1, 256>>>(sents, ntg, iou);
    k2_gemm<<<dim3(NTILE, Bv), 128>>>(video, iou);
    k3_intervideo<<<Sv, 64>>>(video);
    k4_final<<<1, 64>>>((float*)d_out);
}